// round 14
// baseline (speedup 1.0000x reference)
#include <cuda_runtime.h>
#include <cuda_fp16.h>
#include <cstdint>

#define E_  8
#define T_  2048
#define H_  2880
#define D_  2880
#define N2_ 5760

__device__ __half g_xh[(size_t)T_ * H_];
__device__ __half g_w1t[(size_t)E_ * N2_ * H_];
__device__ __half g_w2t[(size_t)E_ * H_ * D_];
__device__ __half g_hidden[(size_t)E_ * T_ * D_];

// ---------------- helpers ----------------
__device__ __forceinline__ unsigned smem_u32(const void* p) {
    return (unsigned)__cvta_generic_to_shared(p);
}
__device__ __forceinline__ void cp16h(__half* s, const __half* g) {
    asm volatile("cp.async.cg.shared.global [%0], [%1], 16;" :: "r"(smem_u32(s)), "l"(g));
}
__device__ __forceinline__ void cp_commit() { asm volatile("cp.async.commit_group;"); }
__device__ __forceinline__ void cp_wait1()  { asm volatile("cp.async.wait_group 1;"); }
__device__ __forceinline__ void cp_wait0()  { asm volatile("cp.async.wait_group 0;"); }

__device__ __forceinline__ void mma16(float* c, const uint32_t* a, const uint32_t* b) {
    asm volatile("mma.sync.aligned.m16n8k16.row.col.f32.f16.f16.f32 "
        "{%0,%1,%2,%3}, {%4,%5,%6,%7}, {%8,%9}, {%0,%1,%2,%3};"
        : "+f"(c[0]), "+f"(c[1]), "+f"(c[2]), "+f"(c[3])
        : "r"(a[0]), "r"(a[1]), "r"(a[2]), "r"(a[3]), "r"(b[0]), "r"(b[1]));
}
__device__ __forceinline__ void ldsm4(uint32_t& r0, uint32_t& r1, uint32_t& r2, uint32_t& r3,
                                      uint32_t addr) {
    asm volatile("ldmatrix.sync.aligned.m8n8.x4.shared.b16 {%0,%1,%2,%3}, [%4];"
        : "=r"(r0), "=r"(r1), "=r"(r2), "=r"(r3) : "r"(addr));
}
__device__ __forceinline__ void ldsm2(uint32_t& r0, uint32_t& r1, uint32_t addr) {
    asm volatile("ldmatrix.sync.aligned.m8n8.x2.shared.b16 {%0,%1}, [%2];"
        : "=r"(r0), "=r"(r1) : "r"(addr));
}

// ---------------- tiling ----------------
constexpr int BM = 128, BN = 160, BK = 64;
constexpr int NT = 256;
constexpr int WN = 40, NF = 5;
constexpr int A_BYTES = BM * 128;
constexpr int B_BYTES = BN * 128;
constexpr int STG_B = A_BYTES + B_BYTES;       // 36864
constexpr int STAGES = 3;
constexpr int SMEM_B = STAGES * STG_B;         // 110592 -> 2 CTAs/SM

// fused w2-transpose role inside gemm1
constexpr int G1_GX = N2_ / BN;                        // 36 GEMM blocks along x
constexpr int TP_TILES = E_ * (H_ / 32) * (D_ / 64);   // 32400 (64-row x 32-col tiles)
constexpr int TP_XBLK = 8;                             // extra x-blocks
constexpr int TP_BLOCKS = TP_XBLK * (T_ / BM) * E_;    // 1024
constexpr int TP_PER_BLK = (TP_TILES + TP_BLOCKS - 1) / TP_BLOCKS;  // 32

template<int ROWS>
__device__ __forceinline__ void load_tile(__half* S, const __half* G, int lda, int tid) {
#pragma unroll
    for (int i = 0; i < ROWS * 8 / NT; i++) {
        int c = tid + i * NT;
        int r = c >> 3, q = c & 7;
        cp16h(S + r * 64 + ((q ^ (r & 7)) << 3), G + (size_t)r * lda + q * 8);
    }
}

__device__ __forceinline__ void offs_A(uint32_t (&aOff)[4], int wm, int lane) {
    const int rr = lane & 7, mm = lane >> 3;
#pragma unroll
    for (int i = 0; i < 4; i++) {
        const int row = wm * 64 + i * 16 + (mm & 1) * 8 + rr;
        aOff[i] = row * 128 + ((((mm >> 1) ^ (row & 7)) & 7) << 4);
    }
}
__device__ __forceinline__ void offs_B(uint32_t (&bOff)[3], int wn, int lane) {
    const int rr = lane & 7, mm = lane >> 3;
#pragma unroll
    for (int jp = 0; jp < 2; jp++) {
        const int row = wn * WN + (jp * 2 + (mm >> 1)) * 8 + rr;
        bOff[jp] = row * 128 + ((((mm & 1) ^ (row & 7)) & 7) << 4);
    }
    {
        const int row = wn * WN + 32 + rr;
        bOff[2] = row * 128 + ((((mm & 1) ^ (row & 7)) & 7) << 4);
    }
}

__device__ __forceinline__ void ldsm_batch(uint32_t sA, uint32_t sB,
                                           const uint32_t (&aOff)[4],
                                           const uint32_t (&bOff)[3],
                                           int ks, uint32_t (&a)[4][4], uint32_t (&b)[NF][2]) {
    const uint32_t kx = ks * 32;
#pragma unroll
    for (int i = 0; i < 4; i++)
        ldsm4(a[i][0], a[i][1], a[i][2], a[i][3], sA + (aOff[i] ^ kx));
    ldsm4(b[0][0], b[0][1], b[1][0], b[1][1], sB + (bOff[0] ^ kx));
    ldsm4(b[2][0], b[2][1], b[3][0], b[3][1], sB + (bOff[1] ^ kx));
    ldsm2(b[4][0], b[4][1], sB + (bOff[2] ^ kx));
}
__device__ __forceinline__ void mma_batch(const uint32_t (&a)[4][4], const uint32_t (&b)[NF][2],
                                          float (&acc)[4][NF][4]) {
#pragma unroll
    for (int i = 0; i < 4; i++)
#pragma unroll
        for (int j = 0; j < NF; j++)
            mma16(acc[i][j], a[i], b[j]);
}

// ================= preprocess =================
__global__ void k_tohalf(const float2* __restrict__ in, __half2* __restrict__ out, size_t n2) {
    size_t i = (size_t)blockIdx.x * blockDim.x + threadIdx.x;
    size_t st = (size_t)gridDim.x * blockDim.x;
    for (; i < n2; i += st) {
        float2 v = in[i];
        out[i] = __floats2half2_rn(v.x, v.y);
    }
}
// [z][R][C] fp32 -> [z][C][R] fp16; 64-row x 32-col tiles, half2 coalesced stores
__global__ void k_transpose_h(const float* __restrict__ in, __half* __restrict__ out, int R, int C) {
    __shared__ float t[64][33];
    const float* iz = in + (size_t)blockIdx.z * R * C;
    __half* oz = out + (size_t)blockIdx.z * R * C;
    const int c0 = blockIdx.x * 32, r0 = blockIdx.y * 64;
    const int tx = threadIdx.x, ty = threadIdx.y;
#pragma unroll
    for (int i = 0; i < 64; i += 8)
        t[ty + i][tx] = iz[(size_t)(r0 + ty + i) * C + c0 + tx];
    __syncthreads();
#pragma unroll
    for (int j = 0; j < 4; j++) {
        const int cc = ty + 8 * j;
        __half2 v = __floats2half2_rn(t[2 * tx][cc], t[2 * tx + 1][cc]);
        *(__half2*)(oz + (size_t)(c0 + cc) * R + r0 + 2 * tx) = v;
    }
}

// ================= GEMM1 (R13 schedule) + fused w2 transpose blocks ========
__global__ void __launch_bounds__(NT, 2)
k_gemm1(const float* __restrict__ b1, const float* __restrict__ routing,
        const float* __restrict__ w2) {
    extern __shared__ __align__(128) char smc[];
    __half* smh = (__half*)smc;
    float* smf = (float*)smc;
    const int tid = threadIdx.x, lane = tid & 31, warp = tid >> 5;

    if (blockIdx.x >= G1_GX) {
        // ---- w2 transpose role: [E][D][H] fp32 -> g_w2t [E][H][D] fp16 ----
        float (*t)[33] = (float (*)[33])smc;
        const int tx = tid & 31, ty = tid >> 5;
        const int bidx = (blockIdx.x - G1_GX) + TP_XBLK * (blockIdx.y + (T_ / BM) * blockIdx.z);
        const int base = bidx * TP_PER_BLK;
        const int lim = (base + TP_PER_BLK < TP_TILES) ? base + TP_PER_BLK : TP_TILES;
        for (int tt = base; tt < lim; tt++) {
            const int e = tt / ((H_ / 32) * (D_ / 64));
            const int rem = tt % ((H_ / 32) * (D_ / 64));
            const int cx = rem / (D_ / 64), ry = rem % (D_ / 64);
            const int c0 = cx * 32, r0 = ry * 64;
            const float* iz = w2 + (size_t)e * D_ * H_;
            __half* oz = g_w2t + (size_t)e * H_ * D_;
#pragma unroll
            for (int i = 0; i < 64; i += 8)
                t[ty + i][tx] = iz[(size_t)(r0 + ty + i) * H_ + c0 + tx];
            __syncthreads();
#pragma unroll
            for (int j = 0; j < 4; j++) {
                const int cc = ty + 8 * j;
                __half2 v = __floats2half2_rn(t[2 * tx][cc], t[2 * tx + 1][cc]);
                *(__half2*)(oz + (size_t)(c0 + cc) * D_ + r0 + 2 * tx) = v;
            }
            __syncthreads();
        }
        return;
    }

    // ---- GEMM role (identical to R13) ----
    const int wm = warp & 1, wn = warp >> 1;
    const int n0 = blockIdx.x * BN;
    const int t0 = blockIdx.y * BM;
    const int e  = blockIdx.z;

    const uint32_t sb = smem_u32(smc);
    const __half* Ag = g_xh + (size_t)t0 * H_;
    const __half* Bg = g_w1t + ((size_t)e * N2_ + n0) * H_;

    uint32_t aOff[4], bOff[3];
    offs_A(aOff, wm, lane);
    offs_B(bOff, wn, lane);

    float acc[4][NF][4];
#pragma unroll
    for (int i = 0; i < 4; i++)
#pragma unroll
        for (int j = 0; j < NF; j++)
#pragma unroll
            for (int q = 0; q < 4; q++) acc[i][j][q] = 0.f;

    constexpr int KT = H_ / BK;   // 45
#pragma unroll
    for (int s = 0; s < 2; s++) {
        load_tile<BM>(smh + s * STG_B / 2, Ag + s * BK, H_, tid);
        load_tile<BN>(smh + (s * STG_B + A_BYTES) / 2, Bg + s * BK, H_, tid);
        cp_commit();
    }

    for (int kt = 0; kt < KT; kt++) {
        if (kt < KT - 1) cp_wait1(); else cp_wait0();
        __syncthreads();
        const int nk = kt + 2;
        if (nk < KT) {
            const int ns = nk % 3;
            load_tile<BM>(smh + ns * STG_B / 2, Ag + nk * BK, H_, tid);
            load_tile<BN>(smh + (ns * STG_B + A_BYTES) / 2, Bg + nk * BK, H_, tid);
            cp_commit();
        }
        const int s = kt % 3;
        const uint32_t sA = sb + s * STG_B, sB = sA + A_BYTES;
        uint32_t a[4][4], b[NF][2];
#pragma unroll
        for (int ks = 0; ks < 4; ks++) {
            ldsm_batch(sA, sB, aOff, bOff, ks, a, b);
            mma_batch(a, b, acc);
        }
    }

    __syncthreads();
    if (tid < BN) smf[tid] = b1[(size_t)e * N2_ + n0 + tid];
    __syncthreads();

    const int ra = lane >> 2, ca2 = 2 * (lane & 3);
#pragma unroll
    for (int i = 0; i < 4; i++)
#pragma unroll
        for (int h = 0; h < 2; h++) {
            const int row = wm * 64 + i * 16 + h * 8 + ra;
            const float rw = routing[(size_t)(t0 + row) * E_ + e];
            __half* gh = g_hidden + ((size_t)e * T_ + t0 + row) * D_ + (n0 >> 1);
#pragma unroll
            for (int j = 0; j < NF; j++) {
                const int C = wn * WN + j * 8 + ca2;
                float gate = acc[i][j][2 * h]     + smf[C];
                float up   = acc[i][j][2 * h + 1] + smf[C + 1];
                gate = fminf(gate, 7.0f);
                up   = fminf(fmaxf(up, -7.0f), 7.0f);
                const float glu = gate / (1.0f + __expf(-1.702f * gate));
                gh[C >> 1] = __float2half_rn((up + 1.0f) * glu * rw);
            }
        }
}

// ================= GEMM2 (exact R13) =================
__global__ void __launch_bounds__(NT, 2)
k_gemm2(const float* __restrict__ b2, const float* __restrict__ routing,
        float* __restrict__ out) {
    extern __shared__ __align__(128) char smc[];
    __half* smh = (__half*)smc;
    float* smf = (float*)smc;
    const int tid = threadIdx.x, lane = tid & 31, warp = tid >> 5;
    const int wm = warp & 1, wn = warp >> 1;
    const int h0 = blockIdx.x * BN;
    const int t0 = blockIdx.y * BM;

    const uint32_t sb = smem_u32(smc);
    uint32_t aOff[4], bOff[3];
    offs_A(aOff, wm, lane);
    offs_B(bOff, wn, lane);

    float acc[4][NF][4];
#pragma unroll
    for (int i = 0; i < 4; i++)
#pragma unroll
        for (int j = 0; j < NF; j++)
#pragma unroll
            for (int q = 0; q < 4; q++) acc[i][j][q] = 0.f;

    constexpr int KPE = D_ / BK;   // 45
    constexpr int KT  = E_ * KPE;  // 360

#pragma unroll
    for (int s = 0; s < 2; s++) {
        load_tile<BM>(smh + s * STG_B / 2, g_hidden + (size_t)t0 * D_ + s * BK, D_, tid);
        load_tile<BN>(smh + (s * STG_B + A_BYTES) / 2, g_w2t + (size_t)h0 * D_ + s * BK, D_, tid);
        cp_commit();
    }

    int ez = 0, kk = 2;
    for (int kt = 0; kt < KT; kt++) {
        if (kt < KT - 1) cp_wait1(); else cp_wait0();
        __syncthreads();
        const int nk = kt + 2;
        if (nk < KT) {
            const int ns = nk % 3;
            load_tile<BM>(smh + ns * STG_B / 2,
                          g_hidden + ((size_t)ez * T_ + t0) * D_ + kk * BK, D_, tid);
            load_tile<BN>(smh + (ns * STG_B + A_BYTES) / 2,
                          g_w2t + ((size_t)ez * H_ + h0) * D_ + kk * BK, D_, tid);
            cp_commit();
            if (++kk == KPE) { kk = 0; ez++; }
        }
        const int s = kt % 3;
        const uint32_t sA = sb + s * STG_B, sB = sA + A_BYTES;
        uint32_t a[4][4], b[NF][2];
#pragma unroll
        for (int ks = 0; ks < 4; ks++) {
            ldsm_batch(sA, sB, aOff, bOff, ks, a, b);
            mma_batch(a, b, acc);
        }
    }

    __syncthreads();
    for (int i = tid; i < E_ * BN; i += NT) {
        const int ee = i / BN, c = i - ee * BN;
        smf[i] = b2[(size_t)ee * H_ + h0 + c];
    }
    __syncthreads();

    const int ra = lane >> 2, ca2 = 2 * (lane & 3);
#pragma unroll
    for (int i = 0; i < 4; i++)
#pragma unroll
        for (int h = 0; h < 2; h++) {
            const int t = t0 + wm * 64 + i * 16 + h * 8 + ra;
            const float4 r03 = ((const float4*)routing)[(size_t)t * 2];
            const float4 r47 = ((const float4*)routing)[(size_t)t * 2 + 1];
            const float rwv[8] = { r03.x, r03.y, r03.z, r03.w, r47.x, r47.y, r47.z, r47.w };
            float* orow = out + (size_t)t * H_ + h0;
#pragma unroll
            for (int j = 0; j < NF; j++) {
                const int C = wn * WN + j * 8 + ca2;
                float v0 = acc[i][j][2 * h];
                float v1 = acc[i][j][2 * h + 1];
#pragma unroll
                for (int ee = 0; ee < E_; ee++) {
                    v0 += rwv[ee] * smf[ee * BN + C];
                    v1 += rwv[ee] * smf[ee * BN + C + 1];
                }
                *(float2*)(orow + C) = make_float2(v0, v1);
            }
        }
}

// ================= host ====================
extern "C" void kernel_launch(void* const* d_in, const int* in_sizes, int n_in,
                              void* d_out, int out_size) {
    const float *x = nullptr, *rw = nullptr, *w1 = nullptr, *b1 = nullptr,
                *w2 = nullptr, *b2 = nullptr;
    for (int i = 0; i < n_in; i++) {
        const long long s = in_sizes[i];
        const float* p = (const float*)d_in[i];
        if      (s == (long long)T_ * H_)        x  = p;
        else if (s == (long long)T_ * E_)        rw = p;
        else if (s == (long long)E_ * H_ * N2_)  w1 = p;
        else if (s == (long long)E_ * N2_)       b1 = p;
        else if (s == (long long)E_ * D_ * H_)   w2 = p;
        else if (s == (long long)E_ * H_)        b2 = p;
    }
    float* out = (float*)d_out;

    void *p_xh, *p_w1t;
    cudaGetSymbolAddress(&p_xh,  g_xh);
    cudaGetSymbolAddress(&p_w1t, g_w1t);

    cudaFuncSetAttribute(k_gemm1, cudaFuncAttributeMaxDynamicSharedMemorySize, SMEM_B);
    cudaFuncSetAttribute(k_gemm2, cudaFuncAttributeMaxDynamicSharedMemorySize, SMEM_B);

    k_tohalf<<<4096, 256>>>((const float2*)x, (__half2*)p_xh, (size_t)T_ * H_ / 2);
    dim3 tb(32, 8);
    k_transpose_h<<<dim3(N2_ / 32, H_ / 64, E_), tb>>>(w1, (__half*)p_w1t, H_, N2_);

    // gemm1: x<36 GEMM blocks; x>=36 fused w2-transpose blocks (use gemm1's idle DRAM)
    k_gemm1<<<dim3(G1_GX + TP_XBLK, T_ / BM, E_), NT, SMEM_B>>>(b1, rw, w2);
    k_gemm2<<<dim3(H_ / BN, T_ / BM), NT, SMEM_B>>>(b2, rw, out);
}

// round 15
// speedup vs baseline: 1.0274x; 1.0274x over previous
#include <cuda_runtime.h>
#include <cuda_fp16.h>
#include <cstdint>

#define E_  8
#define T_  2048
#define H_  2880
#define D_  2880
#define N2_ 5760

__device__ __half g_xh[(size_t)T_ * H_];
__device__ __half g_w1t[(size_t)E_ * N2_ * H_];
__device__ __half g_w2t[(size_t)E_ * H_ * D_];
__device__ __half g_hidden[(size_t)E_ * T_ * D_];

// ---------------- helpers ----------------
__device__ __forceinline__ unsigned smem_u32(const void* p) {
    return (unsigned)__cvta_generic_to_shared(p);
}
__device__ __forceinline__ void cp16h(__half* s, const __half* g) {
    asm volatile("cp.async.cg.shared.global [%0], [%1], 16;" :: "r"(smem_u32(s)), "l"(g));
}
__device__ __forceinline__ void cp_commit() { asm volatile("cp.async.commit_group;"); }
__device__ __forceinline__ void cp_wait1()  { asm volatile("cp.async.wait_group 1;"); }
__device__ __forceinline__ void cp_wait0()  { asm volatile("cp.async.wait_group 0;"); }

__device__ __forceinline__ void mma16(float* c, const uint32_t* a, const uint32_t* b) {
    asm volatile("mma.sync.aligned.m16n8k16.row.col.f32.f16.f16.f32 "
        "{%0,%1,%2,%3}, {%4,%5,%6,%7}, {%8,%9}, {%0,%1,%2,%3};"
        : "+f"(c[0]), "+f"(c[1]), "+f"(c[2]), "+f"(c[3])
        : "r"(a[0]), "r"(a[1]), "r"(a[2]), "r"(a[3]), "r"(b[0]), "r"(b[1]));
}
__device__ __forceinline__ void ldsm4(uint32_t& r0, uint32_t& r1, uint32_t& r2, uint32_t& r3,
                                      uint32_t addr) {
    asm volatile("ldmatrix.sync.aligned.m8n8.x4.shared.b16 {%0,%1,%2,%3}, [%4];"
        : "=r"(r0), "=r"(r1), "=r"(r2), "=r"(r3) : "r"(addr));
}
__device__ __forceinline__ void ldsm2(uint32_t& r0, uint32_t& r1, uint32_t addr) {
    asm volatile("ldmatrix.sync.aligned.m8n8.x2.shared.b16 {%0,%1}, [%2];"
        : "=r"(r0), "=r"(r1) : "r"(addr));
}

// ---------------- tiling ----------------
constexpr int BM = 128, BN = 160, BK = 64;
constexpr int NT = 256;
constexpr int WN = 40, NF = 5;
constexpr int A_BYTES = BM * 128;
constexpr int B_BYTES = BN * 128;
constexpr int STG_B = A_BYTES + B_BYTES;       // 36864
constexpr int STAGES = 3;
constexpr int SMEM_B = STAGES * STG_B;         // 110592 -> 2 CTAs/SM

template<int ROWS>
__device__ __forceinline__ void load_tile(__half* S, const __half* G, int lda, int tid) {
#pragma unroll
    for (int i = 0; i < ROWS * 8 / NT; i++) {
        int c = tid + i * NT;
        int r = c >> 3, q = c & 7;
        cp16h(S + r * 64 + ((q ^ (r & 7)) << 3), G + (size_t)r * lda + q * 8);
    }
}

__device__ __forceinline__ void offs_A(uint32_t (&aOff)[4], int wm, int lane) {
    const int rr = lane & 7, mm = lane >> 3;
#pragma unroll
    for (int i = 0; i < 4; i++) {
        const int row = wm * 64 + i * 16 + (mm & 1) * 8 + rr;
        aOff[i] = row * 128 + ((((mm >> 1) ^ (row & 7)) & 7) << 4);
    }
}
__device__ __forceinline__ void offs_B(uint32_t (&bOff)[3], int wn, int lane) {
    const int rr = lane & 7, mm = lane >> 3;
#pragma unroll
    for (int jp = 0; jp < 2; jp++) {
        const int row = wn * WN + (jp * 2 + (mm >> 1)) * 8 + rr;
        bOff[jp] = row * 128 + ((((mm & 1) ^ (row & 7)) & 7) << 4);
    }
    {
        const int row = wn * WN + 32 + rr;
        bOff[2] = row * 128 + ((((mm & 1) ^ (row & 7)) & 7) << 4);
    }
}

__device__ __forceinline__ void ldsm_batch(uint32_t sA, uint32_t sB,
                                           const uint32_t (&aOff)[4],
                                           const uint32_t (&bOff)[3],
                                           int ks, uint32_t (&a)[4][4], uint32_t (&b)[NF][2]) {
    const uint32_t kx = ks * 32;
#pragma unroll
    for (int i = 0; i < 4; i++)
        ldsm4(a[i][0], a[i][1], a[i][2], a[i][3], sA + (aOff[i] ^ kx));
    ldsm4(b[0][0], b[0][1], b[1][0], b[1][1], sB + (bOff[0] ^ kx));
    ldsm4(b[2][0], b[2][1], b[3][0], b[3][1], sB + (bOff[1] ^ kx));
    ldsm2(b[4][0], b[4][1], sB + (bOff[2] ^ kx));
}
__device__ __forceinline__ void mma_batch(const uint32_t (&a)[4][4], const uint32_t (&b)[NF][2],
                                          float (&acc)[4][NF][4]) {
#pragma unroll
    for (int i = 0; i < 4; i++)
#pragma unroll
        for (int j = 0; j < NF; j++)
            mma16(acc[i][j], a[i], b[j]);
}

// ================= merged preprocess =================
// job layout along gridDim.x:
//   [0, NB1)            : w1 transpose tiles  (R=H, C=N2)
//   [NB1, NB1+NB2)      : w2 transpose tiles  (R=D, C=H)
//   [NB1+NB2, +XB)      : x fp32->fp16 grid-stride copy
constexpr int W1_TX = N2_ / 32, W1_TY = H_ / 64;    // 180 x 45
constexpr int W2_TX = H_ / 32,  W2_TY = D_ / 64;    // 90 x 45
constexpr int NB1 = E_ * W1_TY * W1_TX;             // 64800
constexpr int NB2 = E_ * W2_TY * W2_TX;             // 32400
constexpr int XB  = 512;

__device__ __forceinline__ void transpose_tile(const float* iz, __half* oz, int R,
                                               int c0, int r0, int tx, int ty, int C,
                                               float (*t)[33]) {
#pragma unroll
    for (int i = 0; i < 64; i += 8)
        t[ty + i][tx] = iz[(size_t)(r0 + ty + i) * C + c0 + tx];
    __syncthreads();
#pragma unroll
    for (int j = 0; j < 4; j++) {
        const int cc = ty + 8 * j;
        __half2 v = __floats2half2_rn(t[2 * tx][cc], t[2 * tx + 1][cc]);
        *(__half2*)(oz + (size_t)(c0 + cc) * R + r0 + 2 * tx) = v;
    }
}

__global__ void k_preprocess(const float* __restrict__ x, const float* __restrict__ w1,
                             const float* __restrict__ w2) {
    __shared__ float t[64][33];
    const int bx = blockIdx.x;
    const int tx = threadIdx.x, ty = threadIdx.y;
    if (bx < NB1) {
        const int e = bx / (W1_TY * W1_TX), rem = bx % (W1_TY * W1_TX);
        const int cx = rem / W1_TY, ry = rem % W1_TY;
        transpose_tile(w1 + (size_t)e * H_ * N2_, g_w1t + (size_t)e * N2_ * H_,
                       H_, cx * 32, ry * 64, tx, ty, N2_, t);
    } else if (bx < NB1 + NB2) {
        const int b = bx - NB1;
        const int e = b / (W2_TY * W2_TX), rem = b % (W2_TY * W2_TX);
        const int cx = rem / W2_TY, ry = rem % W2_TY;
        transpose_tile(w2 + (size_t)e * D_ * H_, g_w2t + (size_t)e * H_ * D_,
                       D_, cx * 32, ry * 64, tx, ty, H_, t);
    } else {
        const int b = bx - NB1 - NB2;
        const size_t n2 = (size_t)T_ * H_ / 2;
        size_t i = (size_t)b * 256 + ty * 32 + tx;
        const size_t st = (size_t)XB * 256;
        const float2* in = (const float2*)x;
        __half2* outp = (__half2*)g_xh;
        for (; i < n2; i += st) {
            float2 v = in[i];
            outp[i] = __floats2half2_rn(v.x, v.y);
        }
    }
}

// ================= GEMM1 (exact R13) =================
__global__ void __launch_bounds__(NT, 2)
k_gemm1(const float* __restrict__ b1, const float* __restrict__ routing) {
    extern __shared__ __align__(128) char smc[];
    __half* smh = (__half*)smc;
    float* smf = (float*)smc;
    const int tid = threadIdx.x, lane = tid & 31, warp = tid >> 5;
    const int wm = warp & 1, wn = warp >> 1;
    const int n0 = blockIdx.x * BN;
    const int t0 = blockIdx.y * BM;
    const int e  = blockIdx.z;

    const uint32_t sb = smem_u32(smc);
    const __half* Ag = g_xh + (size_t)t0 * H_;
    const __half* Bg = g_w1t + ((size_t)e * N2_ + n0) * H_;

    uint32_t aOff[4], bOff[3];
    offs_A(aOff, wm, lane);
    offs_B(bOff, wn, lane);

    float acc[4][NF][4];
#pragma unroll
    for (int i = 0; i < 4; i++)
#pragma unroll
        for (int j = 0; j < NF; j++)
#pragma unroll
            for (int q = 0; q < 4; q++) acc[i][j][q] = 0.f;

    constexpr int KT = H_ / BK;   // 45
#pragma unroll
    for (int s = 0; s < 2; s++) {
        load_tile<BM>(smh + s * STG_B / 2, Ag + s * BK, H_, tid);
        load_tile<BN>(smh + (s * STG_B + A_BYTES) / 2, Bg + s * BK, H_, tid);
        cp_commit();
    }

    for (int kt = 0; kt < KT; kt++) {
        if (kt < KT - 1) cp_wait1(); else cp_wait0();
        __syncthreads();
        const int nk = kt + 2;
        if (nk < KT) {
            const int ns = nk % 3;
            load_tile<BM>(smh + ns * STG_B / 2, Ag + nk * BK, H_, tid);
            load_tile<BN>(smh + (ns * STG_B + A_BYTES) / 2, Bg + nk * BK, H_, tid);
            cp_commit();
        }
        const int s = kt % 3;
        const uint32_t sA = sb + s * STG_B, sB = sA + A_BYTES;
        uint32_t a[4][4], b[NF][2];
#pragma unroll
        for (int ks = 0; ks < 4; ks++) {
            ldsm_batch(sA, sB, aOff, bOff, ks, a, b);
            mma_batch(a, b, acc);
        }
    }

    __syncthreads();
    if (tid < BN) smf[tid] = b1[(size_t)e * N2_ + n0 + tid];
    __syncthreads();

    const int ra = lane >> 2, ca2 = 2 * (lane & 3);
#pragma unroll
    for (int i = 0; i < 4; i++)
#pragma unroll
        for (int h = 0; h < 2; h++) {
            const int row = wm * 64 + i * 16 + h * 8 + ra;
            const float rw = routing[(size_t)(t0 + row) * E_ + e];
            __half* gh = g_hidden + ((size_t)e * T_ + t0 + row) * D_ + (n0 >> 1);
#pragma unroll
            for (int j = 0; j < NF; j++) {
                const int C = wn * WN + j * 8 + ca2;
                float gate = acc[i][j][2 * h]     + smf[C];
                float up   = acc[i][j][2 * h + 1] + smf[C + 1];
                gate = fminf(gate, 7.0f);
                up   = fminf(fmaxf(up, -7.0f), 7.0f);
                const float glu = gate / (1.0f + __expf(-1.702f * gate));
                gh[C >> 1] = __float2half_rn((up + 1.0f) * glu * rw);
            }
        }
}

// ================= GEMM2 (R13 + incremental pointers) =================
__global__ void __launch_bounds__(NT, 2)
k_gemm2(const float* __restrict__ b2, const float* __restrict__ routing,
        float* __restrict__ out) {
    extern __shared__ __align__(128) char smc[];
    __half* smh = (__half*)smc;
    float* smf = (float*)smc;
    const int tid = threadIdx.x, lane = tid & 31, warp = tid >> 5;
    const int wm = warp & 1, wn = warp >> 1;
    const int h0 = blockIdx.x * BN;
    const int t0 = blockIdx.y * BM;

    const uint32_t sb = smem_u32(smc);
    uint32_t aOff[4], bOff[3];
    offs_A(aOff, wm, lane);
    offs_B(bOff, wn, lane);

    float acc[4][NF][4];
#pragma unroll
    for (int i = 0; i < 4; i++)
#pragma unroll
        for (int j = 0; j < NF; j++)
#pragma unroll
            for (int q = 0; q < 4; q++) acc[i][j][q] = 0.f;

    constexpr int KPE = D_ / BK;   // 45
    constexpr int KT  = E_ * KPE;  // 360
    // pointer wrap deltas at expert boundary (from kk=KPE-1 to next expert kk=0)
    constexpr size_t A_WRAP = (size_t)T_ * D_ - (D_ - BK);
    constexpr size_t B_WRAP = (size_t)H_ * D_ - (D_ - BK);

    const __half* pA = g_hidden + (size_t)t0 * D_;
    const __half* pB = g_w2t + (size_t)h0 * D_;

#pragma unroll
    for (int s = 0; s < 2; s++) {
        load_tile<BM>(smh + s * STG_B / 2, pA, D_, tid);
        load_tile<BN>(smh + (s * STG_B + A_BYTES) / 2, pB, D_, tid);
        cp_commit();
        pA += BK; pB += BK;
    }

    int kk = 2;                    // k-chunk index (within expert) of next load
    for (int kt = 0; kt < KT; kt++) {
        if (kt < KT - 1) cp_wait1(); else cp_wait0();
        __syncthreads();
        const int nk = kt + 2;
        if (nk < KT) {
            const int ns = nk % 3;
            load_tile<BM>(smh + ns * STG_B / 2, pA, D_, tid);
            load_tile<BN>(smh + (ns * STG_B + A_BYTES) / 2, pB, D_, tid);
            cp_commit();
            if (++kk == KPE) { kk = 0; pA += A_WRAP; pB += B_WRAP; }
            else             { pA += BK; pB += BK; }
        }
        const int s = kt % 3;
        const uint32_t sA = sb + s * STG_B, sB = sA + A_BYTES;
        uint32_t a[4][4], b[NF][2];
#pragma unroll
        for (int ks = 0; ks < 4; ks++) {
            ldsm_batch(sA, sB, aOff, bOff, ks, a, b);
            mma_batch(a, b, acc);
        }
    }

    __syncthreads();
    for (int i = tid; i < E_ * BN; i += NT) {
        const int ee = i / BN, c = i - ee * BN;
        smf[i] = b2[(size_t)ee * H_ + h0 + c];
    }
    __syncthreads();

    const int ra = lane >> 2, ca2 = 2 * (lane & 3);
#pragma unroll
    for (int i = 0; i < 4; i++)
#pragma unroll
        for (int h = 0; h < 2; h++) {
            const int t = t0 + wm * 64 + i * 16 + h * 8 + ra;
            const float4 r03 = ((const float4*)routing)[(size_t)t * 2];
            const float4 r47 = ((const float4*)routing)[(size_t)t * 2 + 1];
            const float rwv[8] = { r03.x, r03.y, r03.z, r03.w, r47.x, r47.y, r47.z, r47.w };
            float* orow = out + (size_t)t * H_ + h0;
#pragma unroll
            for (int j = 0; j < NF; j++) {
                const int C = wn * WN + j * 8 + ca2;
                float v0 = acc[i][j][2 * h];
                float v1 = acc[i][j][2 * h + 1];
#pragma unroll
                for (int ee = 0; ee < E_; ee++) {
                    v0 += rwv[ee] * smf[ee * BN + C];
                    v1 += rwv[ee] * smf[ee * BN + C + 1];
                }
                *(float2*)(orow + C) = make_float2(v0, v1);
            }
        }
}

// ================= host ====================
extern "C" void kernel_launch(void* const* d_in, const int* in_sizes, int n_in,
                              void* d_out, int out_size) {
    const float *x = nullptr, *rw = nullptr, *w1 = nullptr, *b1 = nullptr,
                *w2 = nullptr, *b2 = nullptr;
    for (int i = 0; i < n_in; i++) {
        const long long s = in_sizes[i];
        const float* p = (const float*)d_in[i];
        if      (s == (long long)T_ * H_)        x  = p;
        else if (s == (long long)T_ * E_)        rw = p;
        else if (s == (long long)E_ * H_ * N2_)  w1 = p;
        else if (s == (long long)E_ * N2_)       b1 = p;
        else if (s == (long long)E_ * D_ * H_)   w2 = p;
        else if (s == (long long)E_ * H_)        b2 = p;
    }
    float* out = (float*)d_out;

    cudaFuncSetAttribute(k_gemm1, cudaFuncAttributeMaxDynamicSharedMemorySize, SMEM_B);
    cudaFuncSetAttribute(k_gemm2, cudaFuncAttributeMaxDynamicSharedMemorySize, SMEM_B);

    dim3 tb(32, 8);
    k_preprocess<<<NB1 + NB2 + XB, tb>>>(x, w1, w2);

    k_gemm1<<<dim3(N2_ / BN, T_ / BM, E_), NT, SMEM_B>>>(b1, rw);
    k_gemm2<<<dim3(H_ / BN, T_ / BM), NT, SMEM_B>>>(b2, rw, out);
}

// round 16
// speedup vs baseline: 1.0292x; 1.0018x over previous
#include <cuda_runtime.h>
#include <cuda_fp16.h>
#include <cstdint>

#define E_  8
#define T_  2048
#define H_  2880
#define D_  2880
#define N2_ 5760

__device__ __half g_xh[(size_t)T_ * H_];
__device__ __half g_w1t[(size_t)E_ * N2_ * H_];
__device__ __half g_w2t[(size_t)E_ * H_ * D_];
__device__ __half g_hidden[(size_t)E_ * T_ * D_];

// ---------------- helpers ----------------
__device__ __forceinline__ unsigned smem_u32(const void* p) {
    return (unsigned)__cvta_generic_to_shared(p);
}
__device__ __forceinline__ void cp16h(__half* s, const __half* g) {
    asm volatile("cp.async.cg.shared.global [%0], [%1], 16;" :: "r"(smem_u32(s)), "l"(g));
}
__device__ __forceinline__ void cp_commit() { asm volatile("cp.async.commit_group;"); }
__device__ __forceinline__ void cp_wait1()  { asm volatile("cp.async.wait_group 1;"); }
__device__ __forceinline__ void cp_wait0()  { asm volatile("cp.async.wait_group 0;"); }

__device__ __forceinline__ void mma16(float* c, const uint32_t* a, const uint32_t* b) {
    asm volatile("mma.sync.aligned.m16n8k16.row.col.f32.f16.f16.f32 "
        "{%0,%1,%2,%3}, {%4,%5,%6,%7}, {%8,%9}, {%0,%1,%2,%3};"
        : "+f"(c[0]), "+f"(c[1]), "+f"(c[2]), "+f"(c[3])
        : "r"(a[0]), "r"(a[1]), "r"(a[2]), "r"(a[3]), "r"(b[0]), "r"(b[1]));
}
__device__ __forceinline__ void ldsm4(uint32_t& r0, uint32_t& r1, uint32_t& r2, uint32_t& r3,
                                      uint32_t addr) {
    asm volatile("ldmatrix.sync.aligned.m8n8.x4.shared.b16 {%0,%1,%2,%3}, [%4];"
        : "=r"(r0), "=r"(r1), "=r"(r2), "=r"(r3) : "r"(addr));
}
__device__ __forceinline__ void ldsm2(uint32_t& r0, uint32_t& r1, uint32_t addr) {
    asm volatile("ldmatrix.sync.aligned.m8n8.x2.shared.b16 {%0,%1}, [%2];"
        : "=r"(r0), "=r"(r1) : "r"(addr));
}

// ---------------- tiling ----------------
constexpr int BM = 128, BN = 160, BK = 64;
constexpr int NT = 256;
constexpr int WN = 40, NF = 5;
constexpr int A_BYTES = BM * 128;
constexpr int B_BYTES = BN * 128;
constexpr int STG_B = A_BYTES + B_BYTES;       // 36864
constexpr int STAGES = 3;
constexpr int SMEM_B = STAGES * STG_B;         // 110592 -> 2 CTAs/SM

template<int ROWS>
__device__ __forceinline__ void load_tile(__half* S, const __half* G, int lda, int tid) {
#pragma unroll
    for (int i = 0; i < ROWS * 8 / NT; i++) {
        int c = tid + i * NT;
        int r = c >> 3, q = c & 7;
        cp16h(S + r * 64 + ((q ^ (r & 7)) << 3), G + (size_t)r * lda + q * 8);
    }
}

__device__ __forceinline__ void offs_A(uint32_t (&aOff)[4], int wm, int lane) {
    const int rr = lane & 7, mm = lane >> 3;
#pragma unroll
    for (int i = 0; i < 4; i++) {
        const int row = wm * 64 + i * 16 + (mm & 1) * 8 + rr;
        aOff[i] = row * 128 + ((((mm >> 1) ^ (row & 7)) & 7) << 4);
    }
}
__device__ __forceinline__ void offs_B(uint32_t (&bOff)[3], int wn, int lane) {
    const int rr = lane & 7, mm = lane >> 3;
#pragma unroll
    for (int jp = 0; jp < 2; jp++) {
        const int row = wn * WN + (jp * 2 + (mm >> 1)) * 8 + rr;
        bOff[jp] = row * 128 + ((((mm & 1) ^ (row & 7)) & 7) << 4);
    }
    {
        const int row = wn * WN + 32 + rr;
        bOff[2] = row * 128 + ((((mm & 1) ^ (row & 7)) & 7) << 4);
    }
}

__device__ __forceinline__ void ldsm_batch(uint32_t sA, uint32_t sB,
                                           const uint32_t (&aOff)[4],
                                           const uint32_t (&bOff)[3],
                                           int ks, uint32_t (&a)[4][4], uint32_t (&b)[NF][2]) {
    const uint32_t kx = ks * 32;
#pragma unroll
    for (int i = 0; i < 4; i++)
        ldsm4(a[i][0], a[i][1], a[i][2], a[i][3], sA + (aOff[i] ^ kx));
    ldsm4(b[0][0], b[0][1], b[1][0], b[1][1], sB + (bOff[0] ^ kx));
    ldsm4(b[2][0], b[2][1], b[3][0], b[3][1], sB + (bOff[1] ^ kx));
    ldsm2(b[4][0], b[4][1], sB + (bOff[2] ^ kx));
}
__device__ __forceinline__ void mma_batch(const uint32_t (&a)[4][4], const uint32_t (&b)[NF][2],
                                          float (&acc)[4][NF][4]) {
#pragma unroll
    for (int i = 0; i < 4; i++)
#pragma unroll
        for (int j = 0; j < NF; j++)
            mma16(acc[i][j], a[i], b[j]);
}

// ================= preprocess =================
constexpr int W1_TX = N2_ / 32, W1_TY = H_ / 64;    // 180 x 45
constexpr int W2_TX = H_ / 32,  W2_TY = D_ / 64;    // 90 x 45
constexpr int NB1 = E_ * W1_TY * W1_TX;             // 64800
constexpr int NB2 = E_ * W2_TY * W2_TX;             // 32400
constexpr int XB  = 512;

__device__ __forceinline__ void transpose_tile(const float* iz, __half* oz, int R,
                                               int c0, int r0, int tx, int ty, int C,
                                               float (*t)[33]) {
#pragma unroll
    for (int i = 0; i < 64; i += 8)
        t[ty + i][tx] = iz[(size_t)(r0 + ty + i) * C + c0 + tx];
    __syncthreads();
#pragma unroll
    for (int j = 0; j < 4; j++) {
        const int cc = ty + 8 * j;
        __half2 v = __floats2half2_rn(t[2 * tx][cc], t[2 * tx + 1][cc]);
        *(__half2*)(oz + (size_t)(c0 + cc) * R + r0 + 2 * tx) = v;
    }
}

// pre1: x convert + w1 transpose (needed by gemm1)
__global__ void k_pre1(const float* __restrict__ x, const float* __restrict__ w1) {
    __shared__ float t[64][33];
    const int bx = blockIdx.x;
    const int tx = threadIdx.x, ty = threadIdx.y;
    if (bx < NB1) {
        const int e = bx / (W1_TY * W1_TX), rem = bx % (W1_TY * W1_TX);
        const int cx = rem / W1_TY, ry = rem % W1_TY;
        transpose_tile(w1 + (size_t)e * H_ * N2_, g_w1t + (size_t)e * N2_ * H_,
                       H_, cx * 32, ry * 64, tx, ty, N2_, t);
    } else {
        const int b = bx - NB1;
        const size_t n2 = (size_t)T_ * H_ / 2;
        size_t i = (size_t)b * 256 + ty * 32 + tx;
        const size_t st = (size_t)XB * 256;
        const float2* in = (const float2*)x;
        __half2* outp = (__half2*)g_xh;
        for (; i < n2; i += st) {
            float2 v = in[i];
            outp[i] = __floats2half2_rn(v.x, v.y);
        }
    }
}
// pre2: w2 transpose (needed only by gemm2 — overlapped with gemm1)
__global__ void k_pre2(const float* __restrict__ w2) {
    __shared__ float t[64][33];
    const int bx = blockIdx.x;
    const int tx = threadIdx.x, ty = threadIdx.y;
    const int e = bx / (W2_TY * W2_TX), rem = bx % (W2_TY * W2_TX);
    const int cx = rem / W2_TY, ry = rem % W2_TY;
    transpose_tile(w2 + (size_t)e * D_ * H_, g_w2t + (size_t)e * H_ * D_,
                   D_, cx * 32, ry * 64, tx, ty, H_, t);
}

// ================= GEMM1 (exact R15) =================
__global__ void __launch_bounds__(NT, 2)
k_gemm1(const float* __restrict__ b1, const float* __restrict__ routing) {
    extern __shared__ __align__(128) char smc[];
    __half* smh = (__half*)smc;
    float* smf = (float*)smc;
    const int tid = threadIdx.x, lane = tid & 31, warp = tid >> 5;
    const int wm = warp & 1, wn = warp >> 1;
    const int n0 = blockIdx.x * BN;
    const int t0 = blockIdx.y * BM;
    const int e  = blockIdx.z;

    const uint32_t sb = smem_u32(smc);
    const __half* Ag = g_xh + (size_t)t0 * H_;
    const __half* Bg = g_w1t + ((size_t)e * N2_ + n0) * H_;

    uint32_t aOff[4], bOff[3];
    offs_A(aOff, wm, lane);
    offs_B(bOff, wn, lane);

    float acc[4][NF][4];
#pragma unroll
    for (int i = 0; i < 4; i++)
#pragma unroll
        for (int j = 0; j < NF; j++)
#pragma unroll
            for (int q = 0; q < 4; q++) acc[i][j][q] = 0.f;

    constexpr int KT = H_ / BK;   // 45
#pragma unroll
    for (int s = 0; s < 2; s++) {
        load_tile<BM>(smh + s * STG_B / 2, Ag + s * BK, H_, tid);
        load_tile<BN>(smh + (s * STG_B + A_BYTES) / 2, Bg + s * BK, H_, tid);
        cp_commit();
    }

    for (int kt = 0; kt < KT; kt++) {
        if (kt < KT - 1) cp_wait1(); else cp_wait0();
        __syncthreads();
        const int nk = kt + 2;
        if (nk < KT) {
            const int ns = nk % 3;
            load_tile<BM>(smh + ns * STG_B / 2, Ag + nk * BK, H_, tid);
            load_tile<BN>(smh + (ns * STG_B + A_BYTES) / 2, Bg + nk * BK, H_, tid);
            cp_commit();
        }
        const int s = kt % 3;
        const uint32_t sA = sb + s * STG_B, sB = sA + A_BYTES;
        uint32_t a[4][4], b[NF][2];
#pragma unroll
        for (int ks = 0; ks < 4; ks++) {
            ldsm_batch(sA, sB, aOff, bOff, ks, a, b);
            mma_batch(a, b, acc);
        }
    }

    __syncthreads();
    if (tid < BN) smf[tid] = b1[(size_t)e * N2_ + n0 + tid];
    __syncthreads();

    const int ra = lane >> 2, ca2 = 2 * (lane & 3);
#pragma unroll
    for (int i = 0; i < 4; i++)
#pragma unroll
        for (int h = 0; h < 2; h++) {
            const int row = wm * 64 + i * 16 + h * 8 + ra;
            const float rw = routing[(size_t)(t0 + row) * E_ + e];
            __half* gh = g_hidden + ((size_t)e * T_ + t0 + row) * D_ + (n0 >> 1);
#pragma unroll
            for (int j = 0; j < NF; j++) {
                const int C = wn * WN + j * 8 + ca2;
                float gate = acc[i][j][2 * h]     + smf[C];
                float up   = acc[i][j][2 * h + 1] + smf[C + 1];
                gate = fminf(gate, 7.0f);
                up   = fminf(fmaxf(up, -7.0f), 7.0f);
                const float glu = gate / (1.0f + __expf(-1.702f * gate));
                gh[C >> 1] = __float2half_rn((up + 1.0f) * glu * rw);
            }
        }
}

// ================= GEMM2 (exact R15) =================
__global__ void __launch_bounds__(NT, 2)
k_gemm2(const float* __restrict__ b2, const float* __restrict__ routing,
        float* __restrict__ out) {
    extern __shared__ __align__(128) char smc[];
    __half* smh = (__half*)smc;
    float* smf = (float*)smc;
    const int tid = threadIdx.x, lane = tid & 31, warp = tid >> 5;
    const int wm = warp & 1, wn = warp >> 1;
    const int h0 = blockIdx.x * BN;
    const int t0 = blockIdx.y * BM;

    const uint32_t sb = smem_u32(smc);
    uint32_t aOff[4], bOff[3];
    offs_A(aOff, wm, lane);
    offs_B(bOff, wn, lane);

    float acc[4][NF][4];
#pragma unroll
    for (int i = 0; i < 4; i++)
#pragma unroll
        for (int j = 0; j < NF; j++)
#pragma unroll
            for (int q = 0; q < 4; q++) acc[i][j][q] = 0.f;

    constexpr int KPE = D_ / BK;   // 45
    constexpr int KT  = E_ * KPE;  // 360
    constexpr size_t A_WRAP = (size_t)T_ * D_ - (D_ - BK);
    constexpr size_t B_WRAP = (size_t)H_ * D_ - (D_ - BK);

    const __half* pA = g_hidden + (size_t)t0 * D_;
    const __half* pB = g_w2t + (size_t)h0 * D_;

#pragma unroll
    for (int s = 0; s < 2; s++) {
        load_tile<BM>(smh + s * STG_B / 2, pA, D_, tid);
        load_tile<BN>(smh + (s * STG_B + A_BYTES) / 2, pB, D_, tid);
        cp_commit();
        pA += BK; pB += BK;
    }

    int kk = 2;
    for (int kt = 0; kt < KT; kt++) {
        if (kt < KT - 1) cp_wait1(); else cp_wait0();
        __syncthreads();
        const int nk = kt + 2;
        if (nk < KT) {
            const int ns = nk % 3;
            load_tile<BM>(smh + ns * STG_B / 2, pA, D_, tid);
            load_tile<BN>(smh + (ns * STG_B + A_BYTES) / 2, pB, D_, tid);
            cp_commit();
            if (++kk == KPE) { kk = 0; pA += A_WRAP; pB += B_WRAP; }
            else             { pA += BK; pB += BK; }
        }
        const int s = kt % 3;
        const uint32_t sA = sb + s * STG_B, sB = sA + A_BYTES;
        uint32_t a[4][4], b[NF][2];
#pragma unroll
        for (int ks = 0; ks < 4; ks++) {
            ldsm_batch(sA, sB, aOff, bOff, ks, a, b);
            mma_batch(a, b, acc);
        }
    }

    __syncthreads();
    for (int i = tid; i < E_ * BN; i += NT) {
        const int ee = i / BN, c = i - ee * BN;
        smf[i] = b2[(size_t)ee * H_ + h0 + c];
    }
    __syncthreads();

    const int ra = lane >> 2, ca2 = 2 * (lane & 3);
#pragma unroll
    for (int i = 0; i < 4; i++)
#pragma unroll
        for (int h = 0; h < 2; h++) {
            const int t = t0 + wm * 64 + i * 16 + h * 8 + ra;
            const float4 r03 = ((const float4*)routing)[(size_t)t * 2];
            const float4 r47 = ((const float4*)routing)[(size_t)t * 2 + 1];
            const float rwv[8] = { r03.x, r03.y, r03.z, r03.w, r47.x, r47.y, r47.z, r47.w };
            float* orow = out + (size_t)t * H_ + h0;
#pragma unroll
            for (int j = 0; j < NF; j++) {
                const int C = wn * WN + j * 8 + ca2;
                float v0 = acc[i][j][2 * h];
                float v1 = acc[i][j][2 * h + 1];
#pragma unroll
                for (int ee = 0; ee < E_; ee++) {
                    v0 += rwv[ee] * smf[ee * BN + C];
                    v1 += rwv[ee] * smf[ee * BN + C + 1];
                }
                *(float2*)(orow + C) = make_float2(v0, v1);
            }
        }
}

// ================= host ====================
extern "C" void kernel_launch(void* const* d_in, const int* in_sizes, int n_in,
                              void* d_out, int out_size) {
    const float *x = nullptr, *rw = nullptr, *w1 = nullptr, *b1 = nullptr,
                *w2 = nullptr, *b2 = nullptr;
    for (int i = 0; i < n_in; i++) {
        const long long s = in_sizes[i];
        const float* p = (const float*)d_in[i];
        if      (s == (long long)T_ * H_)        x  = p;
        else if (s == (long long)T_ * E_)        rw = p;
        else if (s == (long long)E_ * H_ * N2_)  w1 = p;
        else if (s == (long long)E_ * N2_)       b1 = p;
        else if (s == (long long)E_ * D_ * H_)   w2 = p;
        else if (s == (long long)E_ * H_)        b2 = p;
    }
    float* out = (float*)d_out;

    // one-time side-stream setup (first call = correctness run, outside capture)
    static cudaStream_t s2 = nullptr;
    static cudaEvent_t evF = nullptr, evJ = nullptr;
    static int sinit = 0;
    if (!sinit) {
        sinit = 1;
        if (cudaStreamCreateWithFlags(&s2, cudaStreamNonBlocking) != cudaSuccess) s2 = nullptr;
        if (s2) {
            if (cudaEventCreateWithFlags(&evF, cudaEventDisableTiming) != cudaSuccess ||
                cudaEventCreateWithFlags(&evJ, cudaEventDisableTiming) != cudaSuccess)
                s2 = nullptr;
        }
        cudaFuncSetAttribute(k_gemm1, cudaFuncAttributeMaxDynamicSharedMemorySize, SMEM_B);
        cudaFuncSetAttribute(k_gemm2, cudaFuncAttributeMaxDynamicSharedMemorySize, SMEM_B);
    }

    dim3 tb(32, 8);
    k_pre1<<<NB1 + XB, tb>>>(x, w1);

    if (s2) {
        // fork after pre1: w2 transpose runs concurrent with gemm1
        cudaEventRecord(evF, 0);
        cudaStreamWaitEvent(s2, evF, 0);
        k_pre2<<<NB2, tb, 0, s2>>>(w2);
        cudaEventRecord(evJ, s2);
    } else {
        k_pre2<<<NB2, tb>>>(w2);
    }

    k_gemm1<<<dim3(N2_ / BN, T_ / BM, E_), NT, SMEM_B>>>(b1, rw);

    if (s2) cudaStreamWaitEvent(0, evJ, 0);
    k_gemm2<<<dim3(H_ / BN, T_ / BM), NT, SMEM_B>>>(b2, rw, out);
}